// round 1
// baseline (speedup 1.0000x reference)
#include <cuda_runtime.h>
#include <cuda_bf16.h>

// ---------------- static device scratch (no allocations allowed) ------------
__device__ int   g_grid[2 * 41 * 160 * 160];   // largest coord grid (S1), reused by all
__device__ float g_bufA[6300000];              // max feature buf: n2(<=192000) * 32
__device__ float g_bufB[6300000];
__device__ float g_sums[256];                  // [0:C) sum, [C:2C) sumsq
__device__ float g_ss[256];                    // [0:C) scale, [C:2C) shift
__device__ float g_wT[710592];                 // all weights transposed to (tap, co, ci)

#define PBLK 8

// ---------------- kernels ---------------------------------------------------
__global__ void k_scatter(const int* __restrict__ coords, int n,
                          int D, int H, int W, int* __restrict__ grid) {
    int i = blockIdx.x * blockDim.x + threadIdx.x;
    if (i < n) {
        int4 c = ((const int4*)coords)[i];
        grid[((c.x * D + c.y) * H + c.z) * W + c.w] = i;
    }
}

// w: (taps, Cin, Cout) -> wT: (taps, Cout, Cin)
__global__ void k_wtrans(const float* __restrict__ w, float* __restrict__ wt,
                         int taps, int Cin, int Cout) {
    int i = blockIdx.x * blockDim.x + threadIdx.x;
    int total = taps * Cin * Cout;
    if (i < total) {
        int co = i % Cout;
        int r  = i / Cout;
        int ci = r % Cin;
        int t  = r / Cin;
        wt[(t * Cout + co) * Cin + ci] = w[i];
    }
}

// Gather sparse conv. blockDim = (Cout, BY). Each (y-row) handles PBLK points.
__global__ void k_conv(const float* __restrict__ fin, float* __restrict__ fout,
                       const int* __restrict__ grid, const int* __restrict__ outc,
                       const float* __restrict__ wT, int n_out, int Cin, int Cout,
                       int KD, int KH, int KW, int sz, int sy, int sx,
                       int pz, int py, int px, int D, int H, int W) {
    extern __shared__ float sh[];
    const int co  = threadIdx.x;
    const int row = threadIdx.y;
    float* fsh = sh + row * (PBLK * Cin);
    const int base = (blockIdx.x * blockDim.y + row) * PBLK;

    int4 pc[PBLK];
    bool pv[PBLK];
#pragma unroll
    for (int p = 0; p < PBLK; p++) {
        int pt = base + p;
        pv[p] = (pt < n_out);
        pc[p] = pv[p] ? ((const int4*)outc)[pt] : make_int4(0, 0, 0, 0);
    }
    float acc[PBLK];
#pragma unroll
    for (int p = 0; p < PBLK; p++) acc[p] = 0.f;

    const int c4 = Cin >> 2;

    for (int kz = 0; kz < KD; kz++)
    for (int ky = 0; ky < KH; ky++)
    for (int kx = 0; kx < KW; kx++) {
        int  idx[PBLK];
        bool any = false;
#pragma unroll
        for (int p = 0; p < PBLK; p++) {
            idx[p] = -1;
            if (pv[p]) {
                int iz = pc[p].y * sz + kz - pz;
                int iy = pc[p].z * sy + ky - py;
                int ix = pc[p].w * sx + kx - px;
                if (iz >= 0 && iz < D && iy >= 0 && iy < H && ix >= 0 && ix < W)
                    idx[p] = grid[((pc[p].x * D + iz) * H + iy) * W + ix];
            }
            any |= (idx[p] >= 0);
        }
        __syncthreads();
#pragma unroll
        for (int p = 0; p < PBLK; p++) {
            for (int ci = co; ci < Cin; ci += Cout)
                fsh[p * Cin + ci] = (idx[p] >= 0) ? fin[idx[p] * Cin + ci] : 0.f;
        }
        __syncthreads();
        if (any) {
            int tap = (kz * KH + ky) * KW + kx;
            const float4* wt = (const float4*)(wT + (size_t)(tap * Cout + co) * Cin);
            const float4* f4 = (const float4*)fsh;
            for (int q = 0; q < c4; q++) {
                float4 wv = wt[q];
#pragma unroll
                for (int p = 0; p < PBLK; p++) {
                    float4 fv = f4[p * c4 + q];
                    acc[p] += fv.x * wv.x + fv.y * wv.y + fv.z * wv.z + fv.w * wv.w;
                }
            }
        }
    }
#pragma unroll
    for (int p = 0; p < PBLK; p++)
        if (pv[p]) fout[(size_t)(base + p) * Cout + co] = acc[p];
}

// per-channel sum & sumsq (shared-atomic partials -> global atomics)
__global__ void k_stats(const float* __restrict__ f, int n, int C,
                        float* __restrict__ sums) {
    extern __shared__ float sh[];   // 2*C
    for (int i = threadIdx.x; i < 2 * C; i += blockDim.x) sh[i] = 0.f;
    __syncthreads();
    int total = n * C;
    for (int idx = blockIdx.x * blockDim.x + threadIdx.x; idx < total;
         idx += gridDim.x * blockDim.x) {
        float v = f[idx];
        int c = idx % C;
        atomicAdd(&sh[c], v);
        atomicAdd(&sh[C + c], v * v);
    }
    __syncthreads();
    for (int i = threadIdx.x; i < 2 * C; i += blockDim.x)
        if (sh[i] != 0.f) atomicAdd(&sums[i], sh[i]);
}

__global__ void k_bnscale(const float* __restrict__ sums, const float* __restrict__ g,
                          const float* __restrict__ b, int n, int C,
                          float* __restrict__ ss) {
    int c = threadIdx.x;
    if (c < C) {
        float inv = 1.f / (float)n;
        float mu  = sums[c] * inv;
        float var = sums[C + c] * inv - mu * mu;
        float sc  = g[c] * rsqrtf(var + 0.001f);
        ss[c]     = sc;
        ss[C + c] = b[c] - mu * sc;
    }
}

__global__ void k_bnrelu(const float* __restrict__ f, const float* __restrict__ ss,
                         int total, int C, float* __restrict__ out) {
    int idx = blockIdx.x * blockDim.x + threadIdx.x;
    if (idx < total) {
        int c = idx % C;
        float v = f[idx] * ss[c] + ss[C + c];
        out[idx] = v > 0.f ? v : 0.f;
    }
}

// ---------------- host orchestration ---------------------------------------
extern "C" void kernel_launch(void* const* d_in, const int* in_sizes, int n_in,
                              void* d_out, int out_size) {
    const float* vf    = (const float*)d_in[0];
    const float* gamma = (const float*)d_in[13];
    const float* beta  = (const float*)d_in[14];
    const int* coords[5];
    int np[5];
    for (int i = 0; i < 5; i++) {
        coords[i] = (const int*)d_in[15 + i];
        np[i]     = in_sizes[15 + i] / 4;
    }

    void* pv;
    cudaGetSymbolAddress(&pv, g_grid); int*   grid = (int*)pv;
    cudaGetSymbolAddress(&pv, g_bufA); float* bufA = (float*)pv;
    cudaGetSymbolAddress(&pv, g_bufB); float* bufB = (float*)pv;
    cudaGetSymbolAddress(&pv, g_sums); float* sums = (float*)pv;
    cudaGetSymbolAddress(&pv, g_ss);   float* ss   = (float*)pv;
    cudaGetSymbolAddress(&pv, g_wT);   float* wT   = (float*)pv;

    static const int CI[12]   = {4, 16, 16, 32, 32, 32, 64, 64, 64, 64, 64, 64};
    static const int CO[12]   = {16, 16, 32, 32, 32, 64, 64, 64, 64, 64, 64, 128};
    static const int OFFc[12] = {0, 16, 32, 64, 96, 128, 192, 256, 320, 384, 448, 512};
    static const int ICX[12]  = {0, 0, 0, 1, 1, 1, 2, 2, 2, 3, 3, 3};
    static const int OCX[12]  = {0, 0, 1, 1, 1, 2, 2, 2, 3, 3, 3, 4};
    static const int SHP[4][3] = {{41, 160, 160}, {21, 80, 80}, {11, 40, 40}, {5, 20, 20}};
    static const int ST[12][3] = {{1,1,1},{1,1,1},{2,2,2},{1,1,1},{1,1,1},{2,2,2},
                                  {1,1,1},{1,1,1},{2,2,2},{1,1,1},{1,1,1},{2,1,1}};
    static const int PD[12][3] = {{1,1,1},{1,1,1},{1,1,1},{1,1,1},{1,1,1},{1,1,1},
                                  {1,1,1},{1,1,1},{0,1,1},{1,1,1},{1,1,1},{0,0,0}};
    static const int KK[12][3] = {{3,3,3},{3,3,3},{3,3,3},{3,3,3},{3,3,3},{3,3,3},
                                  {3,3,3},{3,3,3},{3,3,3},{3,3,3},{3,3,3},{3,1,1}};

    // transpose all weights into g_wT (deterministic, cheap, graph-capturable)
    long woff[13];
    woff[0] = 0;
    for (int l = 0; l < 12; l++) {
        int taps = KK[l][0] * KK[l][1] * KK[l][2];
        woff[l + 1] = woff[l] + (long)taps * CI[l] * CO[l];
    }
    for (int l = 0; l < 12; l++) {
        int taps = KK[l][0] * KK[l][1] * KK[l][2];
        int tot  = taps * CI[l] * CO[l];
        k_wtrans<<<(tot + 255) / 256, 256>>>((const float*)d_in[1 + l],
                                             wT + woff[l], taps, CI[l], CO[l]);
    }

    const float* cur = vf;
    float* bufs[2] = {bufA, bufB};
    int cb = 0;

    for (int l = 0; l < 12; l++) {
        int shp = l / 3;
        int D = SHP[shp][0], H = SHP[shp][1], W = SHP[shp][2];
        int nin  = np[ICX[l]];
        int nout = np[OCX[l]];

        if (l % 3 == 0) {   // coordinate set changes only at layers 0,3,6,9
            cudaMemsetAsync(grid, 0xFF, (size_t)2 * D * H * W * sizeof(int));
            k_scatter<<<(nin + 255) / 256, 256>>>(coords[ICX[l]], nin, D, H, W, grid);
        }

        float* outb = bufs[cb];
        int BY = 128 / CO[l];
        if (BY < 1) BY = 1;
        dim3 blk(CO[l], BY);
        int ptsPerBlk = BY * PBLK;
        int nblk = (nout + ptsPerBlk - 1) / ptsPerBlk;
        size_t shb = (size_t)BY * PBLK * CI[l] * sizeof(float);
        k_conv<<<nblk, blk, shb>>>(cur, outb, grid, coords[OCX[l]], wT + woff[l],
                                   nout, CI[l], CO[l],
                                   KK[l][0], KK[l][1], KK[l][2],
                                   ST[l][0], ST[l][1], ST[l][2],
                                   PD[l][0], PD[l][1], PD[l][2], D, H, W);

        cudaMemsetAsync(sums, 0, 256 * sizeof(float));
        int total = nout * CO[l];
        int sblk = (total + 2047) / 2048;
        if (sblk > 512) sblk = 512;
        if (sblk < 1) sblk = 1;
        k_stats<<<sblk, 256, 2 * CO[l] * sizeof(float)>>>(outb, nout, CO[l], sums);
        k_bnscale<<<1, CO[l]>>>(sums, gamma + OFFc[l], beta + OFFc[l], nout, CO[l], ss);

        float* dst = (l == 11) ? (float*)d_out : outb;
        k_bnrelu<<<(total + 255) / 256, 256>>>(outb, ss, total, CO[l], dst);

        cur = dst;
        cb ^= 1;
    }
}

// round 2
// speedup vs baseline: 1.4914x; 1.4914x over previous
#include <cuda_runtime.h>
#include <cuda_bf16.h>

// ---------------- static device scratch ------------------------------------
__device__ int   g_grid[2 * 41 * 160 * 160];
__device__ float g_bufA[6300000];
__device__ float g_bufB[6300000];
__device__ float g_sums[256];          // [0:C) sum, [C:2C) sumsq
__device__ float g_wT[710592];         // weights as (tap, co, ci)
__device__ int   g_nb[5400000];        // neighbor map [tap][point]

#define PBLK 8

__device__ __forceinline__ void ffma2(unsigned long long& d,
                                      unsigned long long a,
                                      unsigned long long b) {
    asm("fma.rn.f32x2 %0, %1, %2, %0;" : "+l"(d) : "l"(a), "l"(b));
}

// ---------------- utility kernels -------------------------------------------
__global__ void k_fill(int* __restrict__ p, int n) {
    int i = blockIdx.x * blockDim.x + threadIdx.x;
    if (i < n) p[i] = -1;
}

__global__ void k_zero(float* __restrict__ p) { p[threadIdx.x] = 0.f; }

__global__ void k_scatter(const int* __restrict__ coords, int n,
                          int D, int H, int W, int* __restrict__ grid) {
    int i = blockIdx.x * blockDim.x + threadIdx.x;
    if (i < n) {
        int4 c = ((const int4*)coords)[i];
        grid[((c.x * D + c.y) * H + c.z) * W + c.w] = i;
    }
}

struct WPtrs { const float* w[12]; };

// all weights (taps, Cin, Cout) -> (tap, co, ci), one launch
__global__ void k_wtrans_all(WPtrs ws, float* __restrict__ wt) {
    const int CI[12] = {4,16,16,32,32,32,64,64,64,64,64,64};
    const int CO[12] = {16,16,32,32,32,64,64,64,64,64,64,128};
    const int TP[12] = {27,27,27,27,27,27,27,27,27,27,27,3};
    int i = blockIdx.x * blockDim.x + threadIdx.x;
    int off = 0, l, sz = 0;
    for (l = 0; l < 12; l++) {
        sz = TP[l] * CI[l] * CO[l];
        if (i < off + sz) break;
        off += sz;
    }
    if (l >= 12) return;
    int j  = i - off;
    int co = j % CO[l];
    int r  = j / CO[l];
    int ci = r % CI[l];
    int t  = r / CI[l];
    wt[off + ((t * CO[l] + co) * CI[l] + ci)] = ws.w[l][j];
}

// neighbor map: nb[tap * n_out + pt] = input point index or -1
__global__ void k_nbmap(const int* __restrict__ outc, int n_out,
                        const int* __restrict__ grid, int* __restrict__ nb,
                        int KD, int KH, int KW, int sz, int sy, int sx,
                        int pz, int py, int px, int D, int H, int W) {
    int i = blockIdx.x * blockDim.x + threadIdx.x;
    int total = n_out * KD * KH * KW;
    if (i >= total) return;
    int pt  = i % n_out;
    int tap = i / n_out;
    int kx = tap % KW;
    int r  = tap / KW;
    int ky = r % KH;
    int kz = r / KH;
    int4 c = ((const int4*)outc)[pt];
    int iz = c.y * sz + kz - pz;
    int iy = c.z * sy + ky - py;
    int ix = c.w * sx + kx - px;
    int idx = -1;
    if (iz >= 0 && iz < D && iy >= 0 && iy < H && ix >= 0 && ix < W)
        idx = grid[((c.x * D + iz) * H + iy) * W + ix];
    nb[i] = idx;
}

// Gather sparse conv, FFMA2 inner loop. blockDim=(Cout, BY). Row handles PBLK pts.
__global__ void k_conv(const float* __restrict__ fin, float* __restrict__ fout,
                       const int* __restrict__ nb, const float* __restrict__ wT,
                       float* __restrict__ sums,
                       int n_out, int c4, int lc4, int Cout, int taps) {
    extern __shared__ float4 sh4[];
    const int co  = threadIdx.x;
    const int row = threadIdx.y;
    float4* fsh = sh4 + row * (PBLK * c4);
    const int base = (blockIdx.x * blockDim.y + row) * PBLK;

    unsigned long long acc2[PBLK];
#pragma unroll
    for (int p = 0; p < PBLK; p++) acc2[p] = 0ull;

    for (int tap = 0; tap < taps; tap++) {
        int  idx[PBLK];
        bool any = false;
        const int* nbt = nb + tap * n_out;
#pragma unroll
        for (int p = 0; p < PBLK; p++) {
            int pt = base + p;
            idx[p] = (pt < n_out) ? nbt[pt] : -1;
            any |= (idx[p] >= 0);
        }
        __syncthreads();
        for (int t = co; t < PBLK * c4; t += Cout) {
            int p = t >> lc4;
            int q = t & (c4 - 1);
            fsh[t] = (idx[p] >= 0) ? ((const float4*)fin)[idx[p] * c4 + q]
                                   : make_float4(0.f, 0.f, 0.f, 0.f);
        }
        __syncthreads();
        if (any) {
            const ulonglong2* wrow =
                (const ulonglong2*)(wT + (size_t)(tap * Cout + co) * (c4 * 4));
            const ulonglong2* f2 = (const ulonglong2*)fsh;
#pragma unroll 4
            for (int q = 0; q < c4; q++) {
                ulonglong2 wv = wrow[q];
#pragma unroll
                for (int p = 0; p < PBLK; p++) {
                    ulonglong2 fv = f2[p * c4 + q];
                    ffma2(acc2[p], fv.x, wv.x);
                    ffma2(acc2[p], fv.y, wv.y);
                }
            }
        }
    }

    float s = 0.f, s2 = 0.f;
#pragma unroll
    for (int p = 0; p < PBLK; p++) {
        if (base + p < n_out) {
            unsigned lo, hi;
            asm("mov.b64 {%0,%1}, %2;" : "=r"(lo), "=r"(hi) : "l"(acc2[p]));
            float v = __uint_as_float(lo) + __uint_as_float(hi);
            fout[(size_t)(base + p) * Cout + co] = v;
            s  += v;
            s2 += v * v;
        }
    }
    atomicAdd(&sums[co], s);
    atomicAdd(&sums[Cout + co], s2);
}

// BN (scale from sums) + ReLU, fused
__global__ void k_bnrelu(const float* __restrict__ f, const float* __restrict__ sums,
                         const float* __restrict__ g, const float* __restrict__ b,
                         int n, int C, float* __restrict__ out) {
    __shared__ float ssc[128], ssh[128];
    int tid = threadIdx.x;
    if (tid < C) {
        float inv = 1.f / (float)n;
        float mu  = sums[tid] * inv;
        float var = sums[C + tid] * inv - mu * mu;
        float sc  = g[tid] * rsqrtf(var + 0.001f);
        ssc[tid] = sc;
        ssh[tid] = b[tid] - mu * sc;
    }
    __syncthreads();
    int total = n * C;
    for (int idx = blockIdx.x * blockDim.x + tid; idx < total;
         idx += gridDim.x * blockDim.x) {
        int c = idx & (C - 1);
        float v = f[idx] * ssc[c] + ssh[c];
        out[idx] = v > 0.f ? v : 0.f;
    }
}

// ---------------- host orchestration ----------------------------------------
extern "C" void kernel_launch(void* const* d_in, const int* in_sizes, int n_in,
                              void* d_out, int out_size) {
    const float* vf    = (const float*)d_in[0];
    const float* gamma = (const float*)d_in[13];
    const float* beta  = (const float*)d_in[14];
    const int* coords[5];
    int np[5];
    for (int i = 0; i < 5; i++) {
        coords[i] = (const int*)d_in[15 + i];
        np[i]     = in_sizes[15 + i] / 4;
    }

    void* pv;
    cudaGetSymbolAddress(&pv, g_grid); int*   grid = (int*)pv;
    cudaGetSymbolAddress(&pv, g_bufA); float* bufA = (float*)pv;
    cudaGetSymbolAddress(&pv, g_bufB); float* bufB = (float*)pv;
    cudaGetSymbolAddress(&pv, g_sums); float* sums = (float*)pv;
    cudaGetSymbolAddress(&pv, g_wT);   float* wT   = (float*)pv;
    cudaGetSymbolAddress(&pv, g_nb);   int*   nb   = (int*)pv;

    static const int CI[12]   = {4,16,16,32,32,32,64,64,64,64,64,64};
    static const int CO[12]   = {16,16,32,32,32,64,64,64,64,64,64,128};
    static const int OFFc[12] = {0,16,32,64,96,128,192,256,320,384,448,512};
    static const int ICX[12]  = {0,0,0,1,1,1,2,2,2,3,3,3};
    static const int OCX[12]  = {0,0,1,1,1,2,2,2,3,3,3,4};
    static const int SHP[4][3] = {{41,160,160},{21,80,80},{11,40,40},{5,20,20}};
    static const int ST[12][3] = {{1,1,1},{1,1,1},{2,2,2},{1,1,1},{1,1,1},{2,2,2},
                                  {1,1,1},{1,1,1},{2,2,2},{1,1,1},{1,1,1},{2,1,1}};
    static const int PD[12][3] = {{1,1,1},{1,1,1},{1,1,1},{1,1,1},{1,1,1},{1,1,1},
                                  {1,1,1},{1,1,1},{0,1,1},{1,1,1},{1,1,1},{0,0,0}};
    static const int KK[12][3] = {{3,3,3},{3,3,3},{3,3,3},{3,3,3},{3,3,3},{3,3,3},
                                  {3,3,3},{3,3,3},{3,3,3},{3,3,3},{3,3,3},{3,1,1}};

    long woff[13];
    woff[0] = 0;
    for (int l = 0; l < 12; l++) {
        int taps = KK[l][0] * KK[l][1] * KK[l][2];
        woff[l + 1] = woff[l] + (long)taps * CI[l] * CO[l];
    }

    // 1: fused weight transpose
    WPtrs wp;
    for (int l = 0; l < 12; l++) wp.w[l] = (const float*)d_in[1 + l];
    k_wtrans_all<<<(710592 + 255) / 256, 256>>>(wp, wT);

    const float* cur = vf;
    float* bufs[2] = {bufA, bufB};
    int cb = 0;

    for (int l = 0; l < 12; l++) {
        int shp = l / 3;
        int D = SHP[shp][0], H = SHP[shp][1], W = SHP[shp][2];
        int nin  = np[ICX[l]];
        int nout = np[OCX[l]];
        int taps = KK[l][0] * KK[l][1] * KK[l][2];

        if (l % 3 == 0) {   // input coordinate set changes
            int gsz = 2 * D * H * W;
            k_fill<<<(gsz + 255) / 256, 256>>>(grid, gsz);
            k_scatter<<<(nin + 255) / 256, 256>>>(coords[ICX[l]], nin, D, H, W, grid);
        }
        if (l % 3 != 1) {   // conv config changes (layers 1,4,7,10 reuse prev map)
            int tot = nout * taps;
            k_nbmap<<<(tot + 255) / 256, 256>>>(coords[OCX[l]], nout, grid, nb,
                                                KK[l][0], KK[l][1], KK[l][2],
                                                ST[l][0], ST[l][1], ST[l][2],
                                                PD[l][0], PD[l][1], PD[l][2], D, H, W);
        }

        k_zero<<<1, 256>>>(sums);

        float* outb = bufs[cb];
        int Cout = CO[l], Cin = CI[l];
        int c4 = Cin >> 2;
        int lc4 = (c4 == 1) ? 0 : (c4 == 4) ? 2 : (c4 == 8) ? 3 : 4;
        int BY = 128 / Cout;
        if (BY < 1) BY = 1;
        dim3 blk(Cout, BY);
        int ptsPerBlk = BY * PBLK;
        int nblk = (nout + ptsPerBlk - 1) / ptsPerBlk;
        size_t shb = (size_t)BY * PBLK * c4 * sizeof(float4);
        k_conv<<<nblk, blk, shb>>>(cur, outb, nb, wT + woff[l], sums,
                                   nout, c4, lc4, Cout, taps);

        int total = nout * Cout;
        float* dst = (l == 11) ? (float*)d_out : outb;
        int bblk = (total + 255) / 256;
        if (bblk > 2048) bblk = 2048;
        k_bnrelu<<<bblk, 256>>>(outb, sums, gamma + OFFc[l], beta + OFFc[l],
                                nout, Cout, dst);

        cur = dst;
        cb ^= 1;
    }
}